// round 15
// baseline (speedup 1.0000x reference)
#include <cuda_runtime.h>

// N-body all-pairs gravity, fp32, diff-form (precision-safe), IBLK=8.
// Issue-slot bound at ~84% across R3/R4/R6; issue count per interaction is at
// its algebraic floor (13ish), so this round targets the idle 15% of issue
// slots with 8 independent MUFU/FMA chains per thread, and amortizes the
// LDS.128 + loop overhead over 8 i-bodies.

constexpr int NBODY   = 8192;
constexpr int BLOCK   = 256;
constexpr int IBLK    = 8;
constexpr int ISTRIDE = NBODY / IBLK;         // 1024
constexpr int NSPLIT  = 256;                  // j-dimension splits
constexpr int CHUNK   = NBODY / NSPLIT;       // 32 j-bodies per tile

__global__ __launch_bounds__(BLOCK)
void nbody_kernel(const float* __restrict__ pos,
                  const float* __restrict__ mass,
                  float* __restrict__ out)
{
    __shared__ float4 sh[CHUNK];

    const int i0    = blockIdx.x * BLOCK + threadIdx.x;   // [0, 1024)
    const int jBase = blockIdx.y * CHUNK;

    if (threadIdx.x < CHUNK) {
        const int j = jBase + threadIdx.x;
        sh[threadIdx.x] = make_float4(pos[3 * j + 0], pos[3 * j + 1],
                                      pos[3 * j + 2], mass[j]);
    }
    __syncthreads();

    float px[IBLK], py[IBLK], pz[IBLK];
    float fx[IBLK], fy[IBLK], fz[IBLK];
#pragma unroll
    for (int k = 0; k < IBLK; ++k) {
        const int i = i0 + k * ISTRIDE;
        px[k] = pos[3 * i + 0];
        py[k] = pos[3 * i + 1];
        pz[k] = pos[3 * i + 2];
        fx[k] = 0.f; fy[k] = 0.f; fz[k] = 0.f;
    }

#pragma unroll 4
    for (int t = 0; t < CHUNK; ++t) {
        const float4 b = sh[t];          // one LDS.128 serves 8 i-bodies
#pragma unroll
        for (int k = 0; k < IBLK; ++k) { // 8 independent chains
            const float dx = b.x - px[k];
            const float dy = b.y - py[k];
            const float dz = b.z - pz[k];
            const float d2 = fmaf(dx, dx, fmaf(dy, dy, fmaf(dz, dz, 1e-4f)));
            const float r  = rsqrtf(d2);         // MUFU.RSQ
            const float w  = b.w * r * r * r;    // m_j * d^-1.5
            fx[k] = fmaf(w, dx, fx[k]);
            fy[k] = fmaf(w, dy, fy[k]);
            fz[k] = fmaf(w, dz, fz[k]);
        }
    }

#pragma unroll
    for (int k = 0; k < IBLK; ++k) {
        const int i = i0 + k * ISTRIDE;
        atomicAdd(&out[3 * i + 0], fx[k]);
        atomicAdd(&out[3 * i + 1], fy[k]);
        atomicAdd(&out[3 * i + 2], fz[k]);
    }
}

extern "C" void kernel_launch(void* const* d_in, const int* in_sizes, int n_in,
                              void* d_out, int out_size)
{
    const float* pos  = (const float*)d_in[0];   // [8192, 3] fp32
    const float* mass = (const float*)d_in[1];   // [8192]    fp32
    float*       out  = (float*)d_out;           // [8192, 3] fp32

    cudaMemsetAsync(out, 0, (size_t)out_size * sizeof(float));

    dim3 grid(ISTRIDE / BLOCK, NSPLIT);          // 4 x 256 = 1024 CTAs
    nbody_kernel<<<grid, BLOCK>>>(pos, mass, out);
}